// round 1
// baseline (speedup 1.0000x reference)
#include <cuda_runtime.h>
#include <math_constants.h>

// ---------------------------------------------------------------------------
// SelfAttention: out = softmax(causal(scale * (xWq)(xWk)^T)) @ (xWv)
// N=4096, D_IN=D_KQ=D_V=1024, fp32.
//
// Round 1 strategy: fully fp32 SIMT pipeline (numerics: softmax is near
// one-hot; bf16/tf32 scores risk argmax flips vs the fp32 reference).
//   K1 x3 : Q/K/V = x @ W           (SGEMM-NN, 4096x1024x1024)
//   K2    : S = scale * Q @ K^T     (SGEMM-NT, skip tiles fully above diag)
//   K3    : row softmax w/ causal mask, in-place S -> P
//   K4    : out = P @ V             (SGEMM-NN, k-loop truncated at diagonal)
// ---------------------------------------------------------------------------

#define BM 128
#define BN 128
#define BK 16
#define PAD 132   // smem row stride in floats; 132*4B = 528B (16B aligned)

static __device__ float g_Q[4096 * 1024];
static __device__ float g_K[4096 * 1024];
static __device__ float g_V[4096 * 1024];
static __device__ float g_S[4096UL * 4096UL];

// MODE 0: plain C = alpha*A@B        (B is K x N, row-major)
// MODE 1: scores C = alpha*A@B^T     (B is N x K, row-major); skip tiles with
//         bx > by when masked (fully above causal diagonal)
// MODE 2: C = A@B with k-loop limited to (by+1)*BM when masked (P is lower-tri)
template <int MODE, bool TRANSB>
__global__ __launch_bounds__(256, 2)
void gemm_kernel(const float* __restrict__ A, const float* __restrict__ B,
                 float* __restrict__ C, int M, int N, int K,
                 float alpha, const int* __restrict__ maskedp)
{
    __shared__ float As[BK][PAD];
    __shared__ float Bs[BK][PAD];

    const int bx = blockIdx.x;   // N tile
    const int by = blockIdx.y;   // M tile
    const int msk = *maskedp;

    if (MODE == 1) {
        if (msk && bx > by) return;   // tile entirely above the diagonal
    }
    int kEnd = K;
    if (MODE == 2) {
        if (msk) kEnd = min(K, (by + 1) * BM);
    }

    const int tid = threadIdx.x;

    // A-tile (and B-tile in NT case) loader mapping: one float4 per row chunk
    const int ar  = tid >> 2;          // 0..63 (rows; +64 for second half)
    const int akc = (tid & 3) << 2;    // 0,4,8,12 (k offset)
    // B-tile NN loader mapping
    const int bkr = tid >> 5;          // 0..7 (+8)
    const int bc  = (tid & 31) << 2;   // 0..124

    const int ty = tid >> 4;           // 0..15
    const int tx = tid & 15;           // 0..15
    const int rowBase = ty << 3;       // 8 consecutive rows
    const int colBase = tx << 3;       // 8 consecutive cols

    float acc[8][8];
#pragma unroll
    for (int i = 0; i < 8; i++)
#pragma unroll
        for (int j = 0; j < 8; j++) acc[i][j] = 0.0f;

    const float* Aptr = A + (size_t)(by * BM) * K;

    for (int kk = 0; kk < kEnd; kk += BK) {
        // ---- load A tile, transposed into As[k][m] ----
        {
            float4 v0 = *reinterpret_cast<const float4*>(Aptr + (size_t)ar * K + kk + akc);
            float4 v1 = *reinterpret_cast<const float4*>(Aptr + (size_t)(ar + 64) * K + kk + akc);
            As[akc + 0][ar] = v0.x; As[akc + 1][ar] = v0.y;
            As[akc + 2][ar] = v0.z; As[akc + 3][ar] = v0.w;
            As[akc + 0][ar + 64] = v1.x; As[akc + 1][ar + 64] = v1.y;
            As[akc + 2][ar + 64] = v1.z; As[akc + 3][ar + 64] = v1.w;
        }
        // ---- load B tile ----
        if (TRANSB) {
            // B is N x K row-major; Bs[k][n] = B[n][k] (transpose on load)
            const float* Bp = B + (size_t)(bx * BN) * K;
            float4 v0 = *reinterpret_cast<const float4*>(Bp + (size_t)ar * K + kk + akc);
            float4 v1 = *reinterpret_cast<const float4*>(Bp + (size_t)(ar + 64) * K + kk + akc);
            Bs[akc + 0][ar] = v0.x; Bs[akc + 1][ar] = v0.y;
            Bs[akc + 2][ar] = v0.z; Bs[akc + 3][ar] = v0.w;
            Bs[akc + 0][ar + 64] = v1.x; Bs[akc + 1][ar + 64] = v1.y;
            Bs[akc + 2][ar + 64] = v1.z; Bs[akc + 3][ar + 64] = v1.w;
        } else {
            // B is K x N row-major; direct copy into Bs[k][n]
            const float* Bp = B + (size_t)kk * N + bx * BN;
            float4 v0 = *reinterpret_cast<const float4*>(Bp + (size_t)bkr * N + bc);
            float4 v1 = *reinterpret_cast<const float4*>(Bp + (size_t)(bkr + 8) * N + bc);
            *reinterpret_cast<float4*>(&Bs[bkr][bc])     = v0;
            *reinterpret_cast<float4*>(&Bs[bkr + 8][bc]) = v1;
        }
        __syncthreads();

#pragma unroll
        for (int k = 0; k < BK; k++) {
            float a[8], b[8];
            *reinterpret_cast<float4*>(a)     = *reinterpret_cast<const float4*>(&As[k][rowBase]);
            *reinterpret_cast<float4*>(a + 4) = *reinterpret_cast<const float4*>(&As[k][rowBase + 4]);
            *reinterpret_cast<float4*>(b)     = *reinterpret_cast<const float4*>(&Bs[k][colBase]);
            *reinterpret_cast<float4*>(b + 4) = *reinterpret_cast<const float4*>(&Bs[k][colBase + 4]);
#pragma unroll
            for (int i = 0; i < 8; i++)
#pragma unroll
                for (int j = 0; j < 8; j++)
                    acc[i][j] = fmaf(a[i], b[j], acc[i][j]);
        }
        __syncthreads();
    }

    // ---- epilogue: vectorized stores ----
    float* Cp = C + (size_t)(by * BM + rowBase) * N + bx * BN + colBase;
#pragma unroll
    for (int i = 0; i < 8; i++) {
        float4 o0 = make_float4(alpha * acc[i][0], alpha * acc[i][1],
                                alpha * acc[i][2], alpha * acc[i][3]);
        float4 o1 = make_float4(alpha * acc[i][4], alpha * acc[i][5],
                                alpha * acc[i][6], alpha * acc[i][7]);
        *reinterpret_cast<float4*>(Cp + (size_t)i * N)     = o0;
        *reinterpret_cast<float4*>(Cp + (size_t)i * N + 4) = o1;
    }
}

// Row softmax with causal masking applied here (S tiles above the diagonal may
// hold garbage — they are replaced by -inf before the reduction). In-place.
__global__ __launch_bounds__(256)
void softmax_kernel(float* __restrict__ S, const int* __restrict__ maskedp, int n)
{
    __shared__ float sh[4096];
    __shared__ float red[256];

    const int r   = blockIdx.x;
    const int msk = *maskedp;
    const int lim = msk ? (r + 1) : n;
    const int tid = threadIdx.x;

    float m = -CUDART_INF_F;
    for (int j = tid; j < n; j += 256) {
        float v = (j < lim) ? S[(size_t)r * n + j] : -CUDART_INF_F;
        sh[j] = v;
        m = fmaxf(m, v);
    }
    red[tid] = m;
    __syncthreads();
    for (int s = 128; s > 0; s >>= 1) {
        if (tid < s) red[tid] = fmaxf(red[tid], red[tid + s]);
        __syncthreads();
    }
    const float rowmax = red[0];
    __syncthreads();

    float sum = 0.0f;
    for (int j = tid; j < n; j += 256) {
        float e = (j < lim) ? expf(sh[j] - rowmax) : 0.0f;
        sh[j] = e;
        sum += e;
    }
    red[tid] = sum;
    __syncthreads();
    for (int s = 128; s > 0; s >>= 1) {
        if (tid < s) red[tid] += red[tid + s];
        __syncthreads();
    }
    const float inv = 1.0f / red[0];
    __syncthreads();

    for (int j = tid; j < n; j += 256)
        S[(size_t)r * n + j] = sh[j] * inv;
}

extern "C" void kernel_launch(void* const* d_in, const int* in_sizes, int n_in,
                              void* d_out, int out_size)
{
    (void)in_sizes; (void)n_in; (void)out_size;
    const float* x      = (const float*)d_in[0];
    const float* Wq     = (const float*)d_in[1];
    const float* Wk     = (const float*)d_in[2];
    const float* Wv     = (const float*)d_in[3];
    const int*   masked = (const int*)d_in[4];
    float* out = (float*)d_out;

    float *Q, *K, *V, *S;
    cudaGetSymbolAddress((void**)&Q, g_Q);
    cudaGetSymbolAddress((void**)&K, g_K);
    cudaGetSymbolAddress((void**)&V, g_V);
    cudaGetSymbolAddress((void**)&S, g_S);

    const int N = 4096, D = 1024;
    const float scale = 1.0f / 32.0f;   // 1/sqrt(1024), exact

    // K1: Q/K/V projections
    {
        dim3 grid(D / BN, N / BM);
        gemm_kernel<0, false><<<grid, 256>>>(x, Wq, Q, N, D, D, 1.0f, masked);
        gemm_kernel<0, false><<<grid, 256>>>(x, Wk, K, N, D, D, 1.0f, masked);
        gemm_kernel<0, false><<<grid, 256>>>(x, Wv, V, N, D, D, 1.0f, masked);
    }
    // K2: S = scale * Q @ K^T (tiles fully above diagonal skipped when masked)
    {
        dim3 grid(N / BN, N / BM);
        gemm_kernel<1, true><<<grid, 256>>>(Q, K, S, N, N, D, scale, masked);
    }
    // K3: causal-masked row softmax, in place
    softmax_kernel<<<N, 256>>>(S, masked, N);

    // K4: out = P @ V (k-loop truncated at the diagonal when masked)
    {
        dim3 grid(D / BN, N / BM);
        gemm_kernel<2, false><<<grid, 256>>>(S, V, out, N, D, N, 1.0f, masked);
    }
}

// round 6
// speedup vs baseline: 2.6759x; 2.6759x over previous
#include <cuda_runtime.h>
#include <cuda_fp16.h>
#include <math_constants.h>
#include <cstdint>

// ---------------------------------------------------------------------------
// SelfAttention via split-fp16 mma.sync GEMMs (fp32-accurate; plain sm_103 PTX
// only — the harness target has no 'a' feature suffix, so tcgen05 is
// unavailable). Every fp32 matrix is split a = a_hi + a_lo (fp16 each); each
// GEMM computes Ah@Bh + Ah@Bl + Al@Bh with fp32 accumulation (lo*lo dropped,
// ~2^-22 relative). All GEMMs are NT with both operands K-major:
//   proj:   Q/K = x @ W      -> A=x_split,  B=Wt_split (W pre-transposed)
//           V   (epilogue stores V transposed, split)
//   scores: S = scale*Q@K^T  -> skip tiles above causal diagonal
//   softmax: fp32, writes P split (hi/lo fp16)
//   PV:     out = P @ V      -> A=P_split, B=Vt_split; K truncated at diagonal
// ---------------------------------------------------------------------------

#define SN 4096
#define SD 1024
#define BM 128
#define BN 128
#define BKE 64                    // K elems (fp16) per stage = 128 bytes/row
#define NSTAGE 3
#define TILEB 16384               // 128 rows x 128 bytes
#define STAGEB (4 * TILEB)        // Ah, Al, Bh, Bl
#define SMEMB (NSTAGE * STAGEB)   // 196608 bytes

// ------------------------- scratch ----------------------------------------
static __device__ float   g_S[(size_t)SN * SN];
static __device__ __half  g_xh[SN * SD],  g_xl[SN * SD];
static __device__ __half  g_Wth[3][SD * SD], g_Wtl[3][SD * SD];
static __device__ __half  g_Qh[SN * SD],  g_Ql[SN * SD];
static __device__ __half  g_Kh[SN * SD],  g_Kl[SN * SD];
static __device__ __half  g_Vth[(size_t)SD * SN], g_Vtl[(size_t)SD * SN];
static __device__ __half  g_Ph[(size_t)SN * SN],  g_Pl[(size_t)SN * SN];

// ------------------------- PTX helpers ------------------------------------
__device__ __forceinline__ uint32_t smem_u32(const void* p) {
    uint32_t a;
    asm("{ .reg .u64 t; cvta.to.shared.u64 t, %1; cvt.u32.u64 %0, t; }"
        : "=r"(a) : "l"(p));
    return a;
}
__device__ __forceinline__ uint32_t swz(uint32_t o) { return o ^ ((o >> 3) & 0x70); }

__device__ __forceinline__ void cp16(uint32_t dst, const void* src) {
    asm volatile("cp.async.cg.shared.global [%0], [%1], 16;\n" :: "r"(dst), "l"(src));
}
#define CP_COMMIT() asm volatile("cp.async.commit_group;\n" ::: "memory")
#define CP_WAIT1()  asm volatile("cp.async.wait_group 1;\n" ::: "memory")

__device__ __forceinline__ void ldm_x4(uint32_t* r, uint32_t addr) {
    asm volatile("ldmatrix.sync.aligned.m8n8.x4.shared.b16 {%0,%1,%2,%3}, [%4];"
        : "=r"(r[0]), "=r"(r[1]), "=r"(r[2]), "=r"(r[3]) : "r"(addr));
}
__device__ __forceinline__ void ldm_x2(uint32_t* r, uint32_t addr) {
    asm volatile("ldmatrix.sync.aligned.m8n8.x2.shared.b16 {%0,%1}, [%2];"
        : "=r"(r[0]), "=r"(r[1]) : "r"(addr));
}
__device__ __forceinline__ void mma16816(float* c, const uint32_t* a, const uint32_t* b) {
    asm volatile("mma.sync.aligned.m16n8k16.row.col.f32.f16.f16.f32 "
        "{%0,%1,%2,%3}, {%4,%5,%6,%7}, {%8,%9}, {%0,%1,%2,%3};"
        : "+f"(c[0]), "+f"(c[1]), "+f"(c[2]), "+f"(c[3])
        : "r"(a[0]), "r"(a[1]), "r"(a[2]), "r"(a[3]), "r"(b[0]), "r"(b[1]));
}

// ------------------------- GEMM kernel -------------------------------------
// MODE 0: plain. MODE 1: scores (skip bx>by when masked). MODE 2: PV (K trunc).
// EPI 0: split store (Ch,Cl row-major). EPI 1: split transposed store.
// EPI 2: fp32 store alpha*C.
template <int MODE, int EPI>
__global__ void __launch_bounds__(256, 1)
mm_kernel(const __half* __restrict__ Ah, const __half* __restrict__ Al, int lda,
          const __half* __restrict__ Bh, const __half* __restrict__ Bl, int ldb,
          int Kdim, float alpha,
          float* __restrict__ Cf, __half* __restrict__ Ch, __half* __restrict__ Cl,
          int ldc, const int* __restrict__ maskedp)
{
    const int bx = blockIdx.x, by = blockIdx.y;
    const int msk = *maskedp;
    if (MODE == 1 && msk && bx > by) return;

    int kEnd = Kdim;
    if (MODE == 2 && msk) kEnd = (by + 1) * BM;
    const int nIter = kEnd / BKE;       // >= 2 always

    extern __shared__ char smem[];
    const uint32_t sbase = smem_u32(smem);
    const int tid  = threadIdx.x;
    const int wid  = tid >> 5;
    const int lane = tid & 31;
    const int warp_m = wid & 1;         // 2 x 64 rows
    const int warp_n = wid >> 1;        // 4 x 32 cols

    float acc[4][4][4];
#pragma unroll
    for (int mi = 0; mi < 4; mi++)
#pragma unroll
        for (int ni = 0; ni < 4; ni++)
#pragma unroll
            for (int r = 0; r < 4; r++) acc[mi][ni][r] = 0.0f;

    const int aRow0 = by * BM;
    const int bRow0 = bx * BN;

    auto load_stage = [&](int s) {
        const uint32_t st = sbase + (uint32_t)(s % NSTAGE) * STAGEB;
        const int kk = s * BKE;
#pragma unroll
        for (int j = 0; j < 4; j++) {
            const int idx = tid + j * 256;         // 0..1023
            const int r = idx >> 3;
            const int c = idx & 7;                 // 16B chunk
            const uint32_t sw = swz((uint32_t)(r * 128 + c * 16));
            const size_t ka = (size_t)(aRow0 + r) * lda + kk + c * 8;
            const size_t kb = (size_t)(bRow0 + r) * ldb + kk + c * 8;
            cp16(st + 0 * TILEB + sw, Ah + ka);
            cp16(st + 1 * TILEB + sw, Al + ka);
            cp16(st + 2 * TILEB + sw, Bh + kb);
            cp16(st + 3 * TILEB + sw, Bl + kb);
        }
        CP_COMMIT();
    };

    // per-lane ldmatrix byte offsets (within a tile), before k-chunk advance
    const uint32_t aRowB = (uint32_t)(warp_m * 64 + (lane & 15)) * 128 + ((lane >> 4) << 4);
    const uint32_t bRowB = (uint32_t)(warp_n * 32 + (lane & 7))  * 128 + (((lane >> 3) & 1) << 4);

    load_stage(0);
    load_stage(1);

    for (int i = 0; i < nIter; i++) {
        CP_WAIT1();
        __syncthreads();
        if (i + 2 < nIter) load_stage(i + 2);
        else CP_COMMIT();                       // empty group keeps wait_group 1 exact

        const uint32_t st = sbase + (uint32_t)(i % NSTAGE) * STAGEB;
        const uint32_t tAh = st, tAl = st + TILEB, tBh = st + 2 * TILEB, tBl = st + 3 * TILEB;

#pragma unroll
        for (int kc = 0; kc < 4; kc++) {
            const uint32_t kB = (uint32_t)kc * 32;
            uint32_t a[4][4], b0[4][2], b1[4][2];
#pragma unroll
            for (int mi = 0; mi < 4; mi++)
                ldm_x4(a[mi], tAh + swz(aRowB + (uint32_t)(mi * 16) * 128 + kB));
#pragma unroll
            for (int ni = 0; ni < 4; ni++)
                ldm_x2(b0[ni], tBh + swz(bRowB + (uint32_t)(ni * 8) * 128 + kB));
#pragma unroll
            for (int mi = 0; mi < 4; mi++)
#pragma unroll
                for (int ni = 0; ni < 4; ni++)
                    mma16816(acc[mi][ni], a[mi], b0[ni]);      // hi*hi
#pragma unroll
            for (int ni = 0; ni < 4; ni++)
                ldm_x2(b1[ni], tBl + swz(bRowB + (uint32_t)(ni * 8) * 128 + kB));
#pragma unroll
            for (int mi = 0; mi < 4; mi++)
#pragma unroll
                for (int ni = 0; ni < 4; ni++)
                    mma16816(acc[mi][ni], a[mi], b1[ni]);      // hi*lo
#pragma unroll
            for (int mi = 0; mi < 4; mi++)
                ldm_x4(a[mi], tAl + swz(aRowB + (uint32_t)(mi * 16) * 128 + kB));
#pragma unroll
            for (int mi = 0; mi < 4; mi++)
#pragma unroll
                for (int ni = 0; ni < 4; ni++)
                    mma16816(acc[mi][ni], a[mi], b0[ni]);      // lo*hi
        }
        __syncthreads();
    }

    // ---- epilogue: accum -> smem (fp32, padded) -> coalesced global ----
    float* sEpi = (float*)smem;                 // 128 x 132
    __syncthreads();
    {
        const int r0 = warp_m * 64 + (lane >> 2);
        const int c0 = warp_n * 32 + 2 * (lane & 3);
#pragma unroll
        for (int mi = 0; mi < 4; mi++)
#pragma unroll
            for (int ni = 0; ni < 4; ni++) {
                const int rr = r0 + mi * 16;
                const int cc = c0 + ni * 8;
                sEpi[rr * 132 + cc]           = acc[mi][ni][0];
                sEpi[rr * 132 + cc + 1]       = acc[mi][ni][1];
                sEpi[(rr + 8) * 132 + cc]     = acc[mi][ni][2];
                sEpi[(rr + 8) * 132 + cc + 1] = acc[mi][ni][3];
            }
    }
    __syncthreads();

    if (EPI == 2) {
#pragma unroll
        for (int j = 0; j < 16; j++) {
            const int idx = tid + j * 256;       // 0..4095 float4s
            const int row = idx >> 5, c4 = (idx & 31) << 2;
            float4 v = *reinterpret_cast<const float4*>(&sEpi[row * 132 + c4]);
            v.x *= alpha; v.y *= alpha; v.z *= alpha; v.w *= alpha;
            *reinterpret_cast<float4*>(Cf + (size_t)(by * BM + row) * ldc + bx * BN + c4) = v;
        }
    } else if (EPI == 0) {
#pragma unroll
        for (int j = 0; j < 32; j++) {
            const int idx = tid + j * 256;       // 0..8191 half2s
            const int row = idx >> 6, c2 = (idx & 63) << 1;
            const float v0 = sEpi[row * 132 + c2];
            const float v1 = sEpi[row * 132 + c2 + 1];
            const __half h0 = __float2half(v0), h1 = __float2half(v1);
            const __half l0 = __float2half(v0 - __half2float(h0));
            const __half l1 = __float2half(v1 - __half2float(h1));
            const size_t o = (size_t)(by * BM + row) * ldc + bx * BN + c2;
            *reinterpret_cast<__half2*>(Ch + o) = __halves2half2(h0, h1);
            *reinterpret_cast<__half2*>(Cl + o) = __halves2half2(l0, l1);
        }
    } else {  // EPI == 1: transposed split store (V^T)
#pragma unroll
        for (int j = 0; j < 32; j++) {
            const int idx = tid + j * 256;       // 0..8191
            const int c = idx >> 6;              // tile column (feature)
            const int r2 = (idx & 63) << 1;      // two consecutive rows (tokens)
            const float v0 = sEpi[r2 * 132 + c];
            const float v1 = sEpi[(r2 + 1) * 132 + c];
            const __half h0 = __float2half(v0), h1 = __float2half(v1);
            const __half l0 = __float2half(v0 - __half2float(h0));
            const __half l1 = __float2half(v1 - __half2float(h1));
            const size_t o = (size_t)(bx * BN + c) * ldc + by * BM + r2;
            *reinterpret_cast<__half2*>(Ch + o) = __halves2half2(h0, h1);
            *reinterpret_cast<__half2*>(Cl + o) = __halves2half2(l0, l1);
        }
    }
}

// ------------------------- split / transpose -------------------------------
__global__ void __launch_bounds__(256)
split_kernel(const float* __restrict__ in, __half* __restrict__ h,
             __half* __restrict__ l, int n)
{
    int i = blockIdx.x * 256 + threadIdx.x;
    if (i < n) {
        float v = in[i];
        __half hh = __float2half(v);
        h[i] = hh;
        l[i] = __float2half(v - __half2float(hh));
    }
}

__global__ void __launch_bounds__(1024)
tsplit_kernel(const float* __restrict__ W, __half* __restrict__ Th,
              __half* __restrict__ Tl)
{
    __shared__ float t[32][33];
    const int bx = blockIdx.x, by = blockIdx.y;
    const int txx = threadIdx.x, tyy = threadIdx.y;
    t[tyy][txx] = W[(size_t)(by * 32 + tyy) * SD + bx * 32 + txx];
    __syncthreads();
    const int o  = bx * 32 + tyy;      // out-feature (row of Wt)
    const int i2 = by * 32 + txx;      // in-feature  (col of Wt, contiguous)
    const float v = t[txx][tyy];
    __half h = __float2half(v);
    Th[(size_t)o * SD + i2] = h;
    Tl[(size_t)o * SD + i2] = __float2half(v - __half2float(h));
}

// ------------------------- softmax (fp32 -> split P) -----------------------
__global__ void __launch_bounds__(256)
softmax_kernel(const float* __restrict__ S, __half* __restrict__ Ph,
               __half* __restrict__ Pl, const int* __restrict__ maskedp)
{
    __shared__ float sh[SN];
    __shared__ float red[256];
    const int r = blockIdx.x;
    const int lim = (*maskedp) ? (r + 1) : SN;
    const int tid = threadIdx.x;

    float m = -CUDART_INF_F;
    for (int j = tid; j < SN; j += 256) {
        float v = (j < lim) ? S[(size_t)r * SN + j] : -CUDART_INF_F;
        sh[j] = v;
        m = fmaxf(m, v);
    }
    red[tid] = m; __syncthreads();
    for (int s = 128; s > 0; s >>= 1) {
        if (tid < s) red[tid] = fmaxf(red[tid], red[tid + s]);
        __syncthreads();
    }
    const float rowmax = red[0]; __syncthreads();

    float sum = 0.0f;
    for (int j = tid; j < SN; j += 256) {
        float e = (j < lim) ? expf(sh[j] - rowmax) : 0.0f;
        sh[j] = e;
        sum += e;
    }
    red[tid] = sum; __syncthreads();
    for (int s = 128; s > 0; s >>= 1) {
        if (tid < s) red[tid] += red[tid + s];
        __syncthreads();
    }
    const float inv = 1.0f / red[0]; __syncthreads();

    for (int j = tid; j < SN; j += 256) {
        float p = sh[j] * inv;
        __half h = __float2half(p);
        Ph[(size_t)r * SN + j] = h;
        Pl[(size_t)r * SN + j] = __float2half(p - __half2float(h));
    }
}

// ------------------------- host --------------------------------------------
extern "C" void kernel_launch(void* const* d_in, const int* in_sizes, int n_in,
                              void* d_out, int out_size)
{
    (void)in_sizes; (void)n_in; (void)out_size;
    const float* x      = (const float*)d_in[0];
    const float* Wq     = (const float*)d_in[1];
    const float* Wk     = (const float*)d_in[2];
    const float* Wv     = (const float*)d_in[3];
    const int*   masked = (const int*)d_in[4];
    float* out = (float*)d_out;

    float* S;
    __half *xh, *xl, *Wth, *Wtl, *Qh, *Ql, *Kh, *Kl, *Vth, *Vtl, *Ph, *Pl;
    cudaGetSymbolAddress((void**)&S,   g_S);
    cudaGetSymbolAddress((void**)&xh,  g_xh);
    cudaGetSymbolAddress((void**)&xl,  g_xl);
    cudaGetSymbolAddress((void**)&Wth, g_Wth);
    cudaGetSymbolAddress((void**)&Wtl, g_Wtl);
    cudaGetSymbolAddress((void**)&Qh,  g_Qh);
    cudaGetSymbolAddress((void**)&Ql,  g_Ql);
    cudaGetSymbolAddress((void**)&Kh,  g_Kh);
    cudaGetSymbolAddress((void**)&Kl,  g_Kl);
    cudaGetSymbolAddress((void**)&Vth, g_Vth);
    cudaGetSymbolAddress((void**)&Vtl, g_Vtl);
    cudaGetSymbolAddress((void**)&Ph,  g_Ph);
    cudaGetSymbolAddress((void**)&Pl,  g_Pl);

    cudaFuncSetAttribute(mm_kernel<0,0>, cudaFuncAttributeMaxDynamicSharedMemorySize, SMEMB);
    cudaFuncSetAttribute(mm_kernel<0,1>, cudaFuncAttributeMaxDynamicSharedMemorySize, SMEMB);
    cudaFuncSetAttribute(mm_kernel<1,2>, cudaFuncAttributeMaxDynamicSharedMemorySize, SMEMB);
    cudaFuncSetAttribute(mm_kernel<2,2>, cudaFuncAttributeMaxDynamicSharedMemorySize, SMEMB);

    split_kernel<<<(SN * SD + 255) / 256, 256>>>(x, xh, xl, SN * SD);
    dim3 tg(32, 32), tb(32, 32);
    tsplit_kernel<<<tg, tb>>>(Wq, Wth + 0 * SD * SD, Wtl + 0 * SD * SD);
    tsplit_kernel<<<tg, tb>>>(Wk, Wth + 1 * SD * SD, Wtl + 1 * SD * SD);
    tsplit_kernel<<<tg, tb>>>(Wv, Wth + 2 * SD * SD, Wtl + 2 * SD * SD);

    const float scale = 1.0f / 32.0f;
    dim3 gp(SD / BN, SN / BM);        // (8, 32)
    dim3 gs(SN / BN, SN / BM);        // (32, 32)

    mm_kernel<0,0><<<gp, 256, SMEMB>>>(xh, xl, SD, Wth + 0 * SD * SD, Wtl + 0 * SD * SD,
                                       SD, SD, 1.0f, nullptr, Qh, Ql, SD, masked);
    mm_kernel<0,0><<<gp, 256, SMEMB>>>(xh, xl, SD, Wth + 1 * SD * SD, Wtl + 1 * SD * SD,
                                       SD, SD, 1.0f, nullptr, Kh, Kl, SD, masked);
    mm_kernel<0,1><<<gp, 256, SMEMB>>>(xh, xl, SD, Wth + 2 * SD * SD, Wtl + 2 * SD * SD,
                                       SD, SD, 1.0f, nullptr, Vth, Vtl, SN, masked);
    mm_kernel<1,2><<<gs, 256, SMEMB>>>(Qh, Ql, SD, Kh, Kl, SD, SD, scale,
                                       S, nullptr, nullptr, SN, masked);
    softmax_kernel<<<SN, 256>>>(S, Ph, Pl, masked);
    mm_kernel<2,2><<<gp, 256, SMEMB>>>(Ph, Pl, SN, Vth, Vtl, SN, SN, 1.0f,
                                       out, nullptr, nullptr, SD, masked);
}

// round 7
// speedup vs baseline: 3.0583x; 1.1429x over previous
#include <cuda_runtime.h>
#include <cuda_fp16.h>
#include <math_constants.h>
#include <cstdint>

// ---------------------------------------------------------------------------
// SelfAttention via split-fp16 mma.sync GEMMs (fp32-accurate; plain sm_103).
// a = a_hi + a_lo (fp16 each); each GEMM = Ah@Bh + Ah@Bl + Al@Bh, fp32 accum.
// Round 7: CTA tile 128x256 (warp 64x64, NSTAGE=2, x4 B ldmatrix) to cut
// smem-read bytes/FLOP; PV split-K over z to kill the causal straggler tail;
// softmax writes bounded at the row-block diagonal.
// ---------------------------------------------------------------------------

#define SN 4096
#define SD 1024
#define BM 128
#define BN 256
#define BKE 64                    // K elems (fp16) per stage = 128 bytes/row
#define NSTAGE 2
#define ATILEB 16384              // 128 rows x 128 bytes
#define BTILEB 32768              // 256 rows x 128 bytes
#define STAGEB (2 * ATILEB + 2 * BTILEB)   // Ah, Al, Bh, Bl = 98304
#define SMEMB (NSTAGE * STAGEB)   // 196608 bytes

// ------------------------- scratch ----------------------------------------
static __device__ float   g_S[(size_t)SN * SN];
static __device__ float   g_O2[(size_t)SN * SD];
static __device__ __half  g_xh[SN * SD],  g_xl[SN * SD];
static __device__ __half  g_Wth[3][SD * SD], g_Wtl[3][SD * SD];
static __device__ __half  g_Qh[SN * SD],  g_Ql[SN * SD];
static __device__ __half  g_Kh[SN * SD],  g_Kl[SN * SD];
static __device__ __half  g_Vth[(size_t)SD * SN], g_Vtl[(size_t)SD * SN];
static __device__ __half  g_Ph[(size_t)SN * SN],  g_Pl[(size_t)SN * SN];

// ------------------------- PTX helpers ------------------------------------
__device__ __forceinline__ uint32_t smem_u32(const void* p) {
    uint32_t a;
    asm("{ .reg .u64 t; cvta.to.shared.u64 t, %1; cvt.u32.u64 %0, t; }"
        : "=r"(a) : "l"(p));
    return a;
}
__device__ __forceinline__ uint32_t swz(uint32_t o) { return o ^ ((o >> 3) & 0x70); }

__device__ __forceinline__ void cp16(uint32_t dst, const void* src) {
    asm volatile("cp.async.cg.shared.global [%0], [%1], 16;\n" :: "r"(dst), "l"(src));
}
#define CP_COMMIT() asm volatile("cp.async.commit_group;\n" ::: "memory")
#define CP_WAIT1()  asm volatile("cp.async.wait_group 1;\n" ::: "memory")

__device__ __forceinline__ void ldm_x4(uint32_t* r, uint32_t addr) {
    asm volatile("ldmatrix.sync.aligned.m8n8.x4.shared.b16 {%0,%1,%2,%3}, [%4];"
        : "=r"(r[0]), "=r"(r[1]), "=r"(r[2]), "=r"(r[3]) : "r"(addr));
}
__device__ __forceinline__ void mma16816(float* c, const uint32_t* a, const uint32_t* b) {
    asm volatile("mma.sync.aligned.m16n8k16.row.col.f32.f16.f16.f32 "
        "{%0,%1,%2,%3}, {%4,%5,%6,%7}, {%8,%9}, {%0,%1,%2,%3};"
        : "+f"(c[0]), "+f"(c[1]), "+f"(c[2]), "+f"(c[3])
        : "r"(a[0]), "r"(a[1]), "r"(a[2]), "r"(a[3]), "r"(b[0]), "r"(b[1]));
}

// ------------------------- GEMM kernel -------------------------------------
// MODE 0: plain. MODE 1: scores (skip tiles fully above diag when masked).
// MODE 2: PV (K truncated at diagonal; split-K over blockIdx.z, z=1 -> CfAlt).
// EPI 0: split store (Ch,Cl row-major). EPI 1: split transposed store (V^T).
// EPI 2: fp32 store alpha*C.
template <int MODE, int EPI>
__global__ void __launch_bounds__(256, 1)
mm_kernel(const __half* __restrict__ Ah, const __half* __restrict__ Al, int lda,
          const __half* __restrict__ Bh, const __half* __restrict__ Bl, int ldb,
          int Kdim, float alpha,
          float* __restrict__ Cf, float* __restrict__ CfAlt,
          __half* __restrict__ Ch, __half* __restrict__ Cl,
          int ldc, const int* __restrict__ maskedp)
{
    const int bx = blockIdx.x, by = blockIdx.y, bz = blockIdx.z;
    const int msk = *maskedp;
    if (MODE == 1 && msk && 2 * bx > by) return;

    int kStart = 0, kEnd = Kdim;
    if (MODE == 2) {
        if (msk) kEnd = (by + 1) * BM;
        kStart = bz * 2048;
        if (kStart >= kEnd) return;
        kEnd = min(kEnd, kStart + 2048);
    }
    const int nIter = (kEnd - kStart) / BKE;    // >= 2 always

    extern __shared__ char smem[];
    const uint32_t sbase = smem_u32(smem);
    const int tid  = threadIdx.x;
    const int wid  = tid >> 5;
    const int lane = tid & 31;
    const int warp_m = wid & 1;                 // 2 x 64 rows
    const int warp_n = wid >> 1;                // 4 x 64 cols

    float acc[4][8][4];
#pragma unroll
    for (int mi = 0; mi < 4; mi++)
#pragma unroll
        for (int ni = 0; ni < 8; ni++)
#pragma unroll
            for (int r = 0; r < 4; r++) acc[mi][ni][r] = 0.0f;

    const int aRow0 = by * BM;
    const int bRow0 = bx * BN;

    auto load_stage = [&](int s) {
        const uint32_t st = sbase + (uint32_t)(s % NSTAGE) * STAGEB;
        const int kk = kStart + s * BKE;
#pragma unroll
        for (int j = 0; j < 4; j++) {           // A: 128 rows hi+lo
            const int idx = tid + j * 256;      // 0..1023
            const int r = idx >> 3;
            const int c = idx & 7;
            const uint32_t sw = swz((uint32_t)(r * 128 + c * 16));
            const size_t ka = (size_t)(aRow0 + r) * lda + kk + c * 8;
            cp16(st + sw, Ah + ka);
            cp16(st + ATILEB + sw, Al + ka);
        }
#pragma unroll
        for (int j = 0; j < 8; j++) {           // B: 256 rows hi+lo
            const int idx = tid + j * 256;      // 0..2047
            const int r = idx >> 3;
            const int c = idx & 7;
            const uint32_t sw = swz((uint32_t)(r * 128 + c * 16));
            const size_t kb = (size_t)(bRow0 + r) * ldb + kk + c * 8;
            cp16(st + 2 * ATILEB + sw, Bh + kb);
            cp16(st + 2 * ATILEB + BTILEB + sw, Bl + kb);
        }
        CP_COMMIT();
    };

    // per-lane ldmatrix byte offsets (within a tile)
    const uint32_t aRowB = (uint32_t)(warp_m * 64 + (lane & 15)) * 128 + ((lane >> 4) << 4);
    const uint32_t bRowB = (uint32_t)(warp_n * 64 + (lane & 7) + ((lane >> 4) << 3)) * 128
                         + (((lane >> 3) & 1) << 4);

    load_stage(0);
    load_stage(1);

    for (int i = 0; i < nIter; i++) {
        CP_WAIT1();
        __syncthreads();

        const uint32_t st  = sbase + (uint32_t)(i % NSTAGE) * STAGEB;
        const uint32_t tAh = st, tAl = st + ATILEB;
        const uint32_t tBh = st + 2 * ATILEB, tBl = tBh + BTILEB;

#pragma unroll
        for (int kc = 0; kc < 4; kc++) {
            const uint32_t kB = (uint32_t)kc * 32;
            uint32_t a[4][4], bh[8][2];
#pragma unroll
            for (int mi = 0; mi < 4; mi++)
                ldm_x4(a[mi], tAh + swz(aRowB + (uint32_t)(mi * 16) * 128 + kB));
#pragma unroll
            for (int np = 0; np < 4; np++) {
                uint32_t r[4];
                ldm_x4(r, tBh + swz(bRowB + (uint32_t)(np * 16) * 128 + kB));
                bh[2 * np][0] = r[0]; bh[2 * np][1] = r[1];
                bh[2 * np + 1][0] = r[2]; bh[2 * np + 1][1] = r[3];
            }
#pragma unroll
            for (int mi = 0; mi < 4; mi++)
#pragma unroll
                for (int ni = 0; ni < 8; ni++)
                    mma16816(acc[mi][ni], a[mi], bh[ni]);          // hi*hi
            {
                uint32_t bl[8][2];
#pragma unroll
                for (int np = 0; np < 4; np++) {
                    uint32_t r[4];
                    ldm_x4(r, tBl + swz(bRowB + (uint32_t)(np * 16) * 128 + kB));
                    bl[2 * np][0] = r[0]; bl[2 * np][1] = r[1];
                    bl[2 * np + 1][0] = r[2]; bl[2 * np + 1][1] = r[3];
                }
#pragma unroll
                for (int mi = 0; mi < 4; mi++)
#pragma unroll
                    for (int ni = 0; ni < 8; ni++)
                        mma16816(acc[mi][ni], a[mi], bl[ni]);      // hi*lo
            }
#pragma unroll
            for (int mi = 0; mi < 4; mi++)
                ldm_x4(a[mi], tAl + swz(aRowB + (uint32_t)(mi * 16) * 128 + kB));
#pragma unroll
            for (int mi = 0; mi < 4; mi++)
#pragma unroll
                for (int ni = 0; ni < 8; ni++)
                    mma16816(acc[mi][ni], a[mi], bh[ni]);          // lo*hi
        }
        __syncthreads();
        if (i + 2 < nIter) load_stage(i + 2);
        else CP_COMMIT();                       // keep wait_group 1 exact
    }

    // ---- epilogue: accum -> smem (fp32, stride 260) -> coalesced global ----
    float* sEpi = (float*)smem;                 // 128 x 260 floats = 133KB
    __syncthreads();
    {
        const int r0 = warp_m * 64 + (lane >> 2);
        const int c0 = warp_n * 64 + 2 * (lane & 3);
#pragma unroll
        for (int mi = 0; mi < 4; mi++)
#pragma unroll
            for (int ni = 0; ni < 8; ni++) {
                const int rr = r0 + mi * 16;
                const int cc = c0 + ni * 8;
                sEpi[rr * 260 + cc]           = acc[mi][ni][0];
                sEpi[rr * 260 + cc + 1]       = acc[mi][ni][1];
                sEpi[(rr + 8) * 260 + cc]     = acc[mi][ni][2];
                sEpi[(rr + 8) * 260 + cc + 1] = acc[mi][ni][3];
            }
    }
    __syncthreads();

    if (EPI == 2) {
        float* Co = (MODE == 2 && bz == 1) ? CfAlt : Cf;
#pragma unroll
        for (int j = 0; j < 32; j++) {
            const int idx = tid + j * 256;       // 0..8191 float4s
            const int row = idx >> 6, c4 = (idx & 63) << 2;
            float4 v = *reinterpret_cast<const float4*>(&sEpi[row * 260 + c4]);
            v.x *= alpha; v.y *= alpha; v.z *= alpha; v.w *= alpha;
            *reinterpret_cast<float4*>(Co + (size_t)(by * BM + row) * ldc + bx * BN + c4) = v;
        }
    } else if (EPI == 0) {
#pragma unroll
        for (int j = 0; j < 64; j++) {
            const int idx = tid + j * 256;       // 0..16383 half2s
            const int row = idx >> 7, c2 = (idx & 127) << 1;
            const float v0 = sEpi[row * 260 + c2];
            const float v1 = sEpi[row * 260 + c2 + 1];
            const __half h0 = __float2half(v0), h1 = __float2half(v1);
            const __half l0 = __float2half(v0 - __half2float(h0));
            const __half l1 = __float2half(v1 - __half2float(h1));
            const size_t o = (size_t)(by * BM + row) * ldc + bx * BN + c2;
            *reinterpret_cast<__half2*>(Ch + o) = __halves2half2(h0, h1);
            *reinterpret_cast<__half2*>(Cl + o) = __halves2half2(l0, l1);
        }
    } else {  // EPI == 1: transposed split store (V^T)
#pragma unroll
        for (int j = 0; j < 64; j++) {
            const int idx = tid + j * 256;       // 0..16383
            const int c = idx >> 6;              // tile column (feature), 0..255
            const int r2 = (idx & 63) << 1;      // two consecutive tokens
            const float v0 = sEpi[r2 * 260 + c];
            const float v1 = sEpi[(r2 + 1) * 260 + c];
            const __half h0 = __float2half(v0), h1 = __float2half(v1);
            const __half l0 = __float2half(v0 - __half2float(h0));
            const __half l1 = __float2half(v1 - __half2float(h1));
            const size_t o = (size_t)(bx * BN + c) * ldc + by * BM + r2;
            *reinterpret_cast<__half2*>(Ch + o) = __halves2half2(h0, h1);
            *reinterpret_cast<__half2*>(Cl + o) = __halves2half2(l0, l1);
        }
    }
}

// ------------------------- split / transpose -------------------------------
__global__ void __launch_bounds__(256)
split_kernel(const float* __restrict__ in, __half* __restrict__ h,
             __half* __restrict__ l, int n)
{
    int i = blockIdx.x * 256 + threadIdx.x;
    if (i < n) {
        float v = in[i];
        __half hh = __float2half(v);
        h[i] = hh;
        l[i] = __float2half(v - __half2float(hh));
    }
}

__global__ void __launch_bounds__(1024)
tsplit_kernel(const float* __restrict__ W, __half* __restrict__ Th,
              __half* __restrict__ Tl)
{
    __shared__ float t[32][33];
    const int bx = blockIdx.x, by = blockIdx.y;
    const int txx = threadIdx.x, tyy = threadIdx.y;
    t[tyy][txx] = W[(size_t)(by * 32 + tyy) * SD + bx * 32 + txx];
    __syncthreads();
    const int o  = bx * 32 + tyy;
    const int i2 = by * 32 + txx;
    const float v = t[txx][tyy];
    __half h = __float2half(v);
    Th[(size_t)o * SD + i2] = h;
    Tl[(size_t)o * SD + i2] = __float2half(v - __half2float(h));
}

// ------------------------- softmax (fp32 -> split P) -----------------------
__global__ void __launch_bounds__(256)
softmax_kernel(const float* __restrict__ S, __half* __restrict__ Ph,
               __half* __restrict__ Pl, const int* __restrict__ maskedp)
{
    __shared__ float sh[SN];
    __shared__ float red[256];
    const int r = blockIdx.x;
    const int msk = *maskedp;
    const int lim = msk ? (r + 1) : SN;
    const int limw = msk ? ((lim + 127) & ~127) : SN;   // PV never reads past this
    const int tid = threadIdx.x;

    float m = -CUDART_INF_F;
    for (int j = tid; j < lim; j += 256) {
        float v = S[(size_t)r * SN + j];
        sh[j] = v;
        m = fmaxf(m, v);
    }
    red[tid] = m; __syncthreads();
    for (int s = 128; s > 0; s >>= 1) {
        if (tid < s) red[tid] = fmaxf(red[tid], red[tid + s]);
        __syncthreads();
    }
    const float rowmax = red[0]; __syncthreads();

    float sum = 0.0f;
    for (int j = tid; j < lim; j += 256) {
        float e = expf(sh[j] - rowmax);
        sh[j] = e;
        sum += e;
    }
    red[tid] = sum; __syncthreads();
    for (int s = 128; s > 0; s >>= 1) {
        if (tid < s) red[tid] += red[tid + s];
        __syncthreads();
    }
    const float inv = 1.0f / red[0]; __syncthreads();

    for (int j = tid; j < limw; j += 256) {
        float p = (j < lim) ? sh[j] * inv : 0.0f;
        __half h = __float2half(p);
        Ph[(size_t)r * SN + j] = h;
        Pl[(size_t)r * SN + j] = __float2half(p - __half2float(h));
    }
}

// ------------------------- PV split-K reduce -------------------------------
__global__ void __launch_bounds__(256)
add_kernel(float* __restrict__ out, const float* __restrict__ part)
{
    const size_t i = ((size_t)2048 * SD) + ((size_t)blockIdx.x * 256 + threadIdx.x) * 4;
    float4 a = *reinterpret_cast<const float4*>(out + i);
    float4 b = *reinterpret_cast<const float4*>(part + i);
    a.x += b.x; a.y += b.y; a.z += b.z; a.w += b.w;
    *reinterpret_cast<float4*>(out + i) = a;
}

// ------------------------- host --------------------------------------------
extern "C" void kernel_launch(void* const* d_in, const int* in_sizes, int n_in,
                              void* d_out, int out_size)
{
    (void)in_sizes; (void)n_in; (void)out_size;
    const float* x      = (const float*)d_in[0];
    const float* Wq     = (const float*)d_in[1];
    const float* Wk     = (const float*)d_in[2];
    const float* Wv     = (const float*)d_in[3];
    const int*   masked = (const int*)d_in[4];
    float* out = (float*)d_out;

    float *S, *O2;
    __half *xh, *xl, *Wth, *Wtl, *Qh, *Ql, *Kh, *Kl, *Vth, *Vtl, *Ph, *Pl;
    cudaGetSymbolAddress((void**)&S,   g_S);
    cudaGetSymbolAddress((void**)&O2,  g_O2);
    cudaGetSymbolAddress((void**)&xh,  g_xh);
    cudaGetSymbolAddress((void**)&xl,  g_xl);
    cudaGetSymbolAddress((void**)&Wth, g_Wth);
    cudaGetSymbolAddress((void**)&Wtl, g_Wtl);
    cudaGetSymbolAddress((void**)&Qh,  g_Qh);
    cudaGetSymbolAddress((void**)&Ql,  g_Ql);
    cudaGetSymbolAddress((void**)&Kh,  g_Kh);
    cudaGetSymbolAddress((void**)&Kl,  g_Kl);
    cudaGetSymbolAddress((void**)&Vth, g_Vth);
    cudaGetSymbolAddress((void**)&Vtl, g_Vtl);
    cudaGetSymbolAddress((void**)&Ph,  g_Ph);
    cudaGetSymbolAddress((void**)&Pl,  g_Pl);

    cudaFuncSetAttribute(mm_kernel<0,0>, cudaFuncAttributeMaxDynamicSharedMemorySize, SMEMB);
    cudaFuncSetAttribute(mm_kernel<0,1>, cudaFuncAttributeMaxDynamicSharedMemorySize, SMEMB);
    cudaFuncSetAttribute(mm_kernel<1,2>, cudaFuncAttributeMaxDynamicSharedMemorySize, SMEMB);
    cudaFuncSetAttribute(mm_kernel<2,2>, cudaFuncAttributeMaxDynamicSharedMemorySize, SMEMB);

    split_kernel<<<(SN * SD + 255) / 256, 256>>>(x, xh, xl, SN * SD);
    dim3 tg(32, 32), tb(32, 32);
    tsplit_kernel<<<tg, tb>>>(Wq, Wth + 0 * SD * SD, Wtl + 0 * SD * SD);
    tsplit_kernel<<<tg, tb>>>(Wk, Wth + 1 * SD * SD, Wtl + 1 * SD * SD);
    tsplit_kernel<<<tg, tb>>>(Wv, Wth + 2 * SD * SD, Wtl + 2 * SD * SD);

    const float scale = 1.0f / 32.0f;
    dim3 gp(SD / BN, SN / BM);        // (4, 32)
    dim3 gs(SN / BN, SN / BM);        // (16, 32)
    dim3 gv(SD / BN, SN / BM, 2);     // (4, 32, 2) split-K

    mm_kernel<0,0><<<gp, 256, SMEMB>>>(xh, xl, SD, Wth + 0 * SD * SD, Wtl + 0 * SD * SD,
                                       SD, SD, 1.0f, nullptr, nullptr, Qh, Ql, SD, masked);
    mm_kernel<0,0><<<gp, 256, SMEMB>>>(xh, xl, SD, Wth + 1 * SD * SD, Wtl + 1 * SD * SD,
                                       SD, SD, 1.0f, nullptr, nullptr, Kh, Kl, SD, masked);
    mm_kernel<0,1><<<gp, 256, SMEMB>>>(xh, xl, SD, Wth + 2 * SD * SD, Wtl + 2 * SD * SD,
                                       SD, SD, 1.0f, nullptr, nullptr, Vth, Vtl, SN, masked);
    mm_kernel<1,2><<<gs, 256, SMEMB>>>(Qh, Ql, SD, Kh, Kl, SD, SD, scale,
                                       S, nullptr, nullptr, nullptr, SN, masked);
    softmax_kernel<<<SN, 256>>>(S, Ph, Pl, masked);
    mm_kernel<2,2><<<gv, 256, SMEMB>>>(Ph, Pl, SN, Vth, Vtl, SN, SN, 1.0f,
                                       out, O2, nullptr, nullptr, SD, masked);
    add_kernel<<<2048, 256>>>(out, O2);
}

// round 8
// speedup vs baseline: 3.3716x; 1.1025x over previous
#include <cuda_runtime.h>
#include <cuda_fp16.h>
#include <math_constants.h>
#include <cstdint>

// ---------------------------------------------------------------------------
// SelfAttention via split-fp16 mma.sync GEMMs (fp32-accurate; plain sm_103).
// a = a_hi + a_lo (fp16 each); GEMMs use 3 products (Ah@Bh + Ah@Bl + Al@Bh)
// except PV which uses 2 (Ph@Vh + Ph@Vl; Pl dropped, ~2^-11 relative).
// Round 8: fused QKV projection launch (fills SMs; scores becomes the
// 6th launch so ncu -s 5 captures it); 2-product PV; softmax writes Ph only.
// ---------------------------------------------------------------------------

#define SN 4096
#define SD 1024
#define BM 128
#define BN 256
#define BKE 64                    // K elems (fp16) per stage = 128 bytes/row
#define NSTAGE 2
#define ATILEB 16384              // 128 rows x 128 bytes
#define BTILEB 32768              // 256 rows x 128 bytes
#define STAGEB (2 * ATILEB + 2 * BTILEB)   // 98304
#define SMEMB (NSTAGE * STAGEB)   // 196608 bytes

// ------------------------- scratch ----------------------------------------
static __device__ float   g_S[(size_t)SN * SN];
static __device__ float   g_O2[(size_t)SN * SD];
static __device__ __half  g_xh[SN * SD],  g_xl[SN * SD];
static __device__ __half  g_Wth[3][SD * SD], g_Wtl[3][SD * SD];
static __device__ __half  g_Qh[SN * SD],  g_Ql[SN * SD];
static __device__ __half  g_Kh[SN * SD],  g_Kl[SN * SD];
static __device__ __half  g_Vth[(size_t)SD * SN], g_Vtl[(size_t)SD * SN];
static __device__ __half  g_Ph[(size_t)SN * SN];

// ------------------------- PTX helpers ------------------------------------
__device__ __forceinline__ uint32_t smem_u32(const void* p) {
    uint32_t a;
    asm("{ .reg .u64 t; cvta.to.shared.u64 t, %1; cvt.u32.u64 %0, t; }"
        : "=r"(a) : "l"(p));
    return a;
}
__device__ __forceinline__ uint32_t swz(uint32_t o) { return o ^ ((o >> 3) & 0x70); }

__device__ __forceinline__ void cp16(uint32_t dst, const void* src) {
    asm volatile("cp.async.cg.shared.global [%0], [%1], 16;\n" :: "r"(dst), "l"(src));
}
#define CP_COMMIT() asm volatile("cp.async.commit_group;\n" ::: "memory")
#define CP_WAIT1()  asm volatile("cp.async.wait_group 1;\n" ::: "memory")

__device__ __forceinline__ void ldm_x4(uint32_t* r, uint32_t addr) {
    asm volatile("ldmatrix.sync.aligned.m8n8.x4.shared.b16 {%0,%1,%2,%3}, [%4];"
        : "=r"(r[0]), "=r"(r[1]), "=r"(r[2]), "=r"(r[3]) : "r"(addr));
}
__device__ __forceinline__ void mma16816(float* c, const uint32_t* a, const uint32_t* b) {
    asm volatile("mma.sync.aligned.m16n8k16.row.col.f32.f16.f16.f32 "
        "{%0,%1,%2,%3}, {%4,%5,%6,%7}, {%8,%9}, {%0,%1,%2,%3};"
        : "+f"(c[0]), "+f"(c[1]), "+f"(c[2]), "+f"(c[3])
        : "r"(a[0]), "r"(a[1]), "r"(a[2]), "r"(a[3]), "r"(b[0]), "r"(b[1]));
}

__device__ __forceinline__ void split_store2(__half* Hh, __half* Hl, size_t o,
                                             float v0, float v1) {
    const __half h0 = __float2half(v0), h1 = __float2half(v1);
    const __half l0 = __float2half(v0 - __half2float(h0));
    const __half l1 = __float2half(v1 - __half2float(h1));
    *reinterpret_cast<__half2*>(Hh + o) = __halves2half2(h0, h1);
    *reinterpret_cast<__half2*>(Hl + o) = __halves2half2(l0, l1);
}

// ------------------------- GEMM kernel -------------------------------------
// MODE 0: plain. MODE 1: scores (skip tiles fully above diag when masked).
// MODE 2: PV (K truncated at diagonal; split-K over blockIdx.z, z=1 -> CfAlt).
// EPI 2: fp32 store alpha*C.  EPI 3: fused QKV dispatch (bx>>2 selects weight;
//        w<2 -> row-major split store (Q/K), w==2 -> transposed split (V^T)).
// NPROD: 3 = full split, 2 = skip A_lo (loads and MMAs).
template <int MODE, int EPI, int NPROD>
__global__ void __launch_bounds__(256, 1)
mm_kernel(const __half* __restrict__ Ah, const __half* __restrict__ Al, int lda,
          const __half* __restrict__ Bh, const __half* __restrict__ Bl, int ldb,
          int Kdim, float alpha,
          float* __restrict__ Cf, float* __restrict__ CfAlt,
          __half* __restrict__ Qh, __half* __restrict__ Ql,
          __half* __restrict__ Kh, __half* __restrict__ Kl,
          __half* __restrict__ Vth, __half* __restrict__ Vtl,
          int ldc, const int* __restrict__ maskedp)
{
    const int bx = blockIdx.x, by = blockIdx.y, bz = blockIdx.z;
    const int msk = *maskedp;
    if (MODE == 1 && msk && 2 * bx > by) return;

    int kStart = 0, kEnd = Kdim;
    if (MODE == 2) {
        if (msk) kEnd = (by + 1) * BM;
        kStart = bz * 2048;
        if (kStart >= kEnd) return;
        kEnd = min(kEnd, kStart + 2048);
    }
    const int nIter = (kEnd - kStart) / BKE;    // >= 2 always

    // effective B pointer / column base (EPI3 packs 3 weights along bx)
    const __half* BhE = Bh;
    const __half* BlE = Bl;
    int bCol0 = bx * BN;
    int wsel = 0;
    if (EPI == 3) {
        wsel = bx >> 2;
        BhE = Bh + (size_t)wsel * SD * SD;
        BlE = Bl + (size_t)wsel * SD * SD;
        bCol0 = (bx & 3) * BN;
    }

    extern __shared__ char smem[];
    const uint32_t sbase = smem_u32(smem);
    const int tid  = threadIdx.x;
    const int wid  = tid >> 5;
    const int lane = tid & 31;
    const int warp_m = wid & 1;                 // 2 x 64 rows
    const int warp_n = wid >> 1;                // 4 x 64 cols

    float acc[4][8][4];
#pragma unroll
    for (int mi = 0; mi < 4; mi++)
#pragma unroll
        for (int ni = 0; ni < 8; ni++)
#pragma unroll
            for (int r = 0; r < 4; r++) acc[mi][ni][r] = 0.0f;

    const int aRow0 = by * BM;

    auto load_stage = [&](int s) {
        const uint32_t st = sbase + (uint32_t)(s % NSTAGE) * STAGEB;
        const int kk = kStart + s * BKE;
#pragma unroll
        for (int j = 0; j < 4; j++) {           // A: 128 rows (hi, +lo if NPROD=3)
            const int idx = tid + j * 256;
            const int r = idx >> 3;
            const int c = idx & 7;
            const uint32_t sw = swz((uint32_t)(r * 128 + c * 16));
            const size_t ka = (size_t)(aRow0 + r) * lda + kk + c * 8;
            cp16(st + sw, Ah + ka);
            if (NPROD == 3) cp16(st + ATILEB + sw, Al + ka);
        }
#pragma unroll
        for (int j = 0; j < 8; j++) {           // B: 256 rows hi+lo
            const int idx = tid + j * 256;
            const int r = idx >> 3;
            const int c = idx & 7;
            const uint32_t sw = swz((uint32_t)(r * 128 + c * 16));
            const size_t kb = (size_t)(bCol0 + r) * ldb + kk + c * 8;
            cp16(st + 2 * ATILEB + sw, BhE + kb);
            cp16(st + 2 * ATILEB + BTILEB + sw, BlE + kb);
        }
        CP_COMMIT();
    };

    const uint32_t aRowB = (uint32_t)(warp_m * 64 + (lane & 15)) * 128 + ((lane >> 4) << 4);
    const uint32_t bRowB = (uint32_t)(warp_n * 64 + (lane & 7) + ((lane >> 4) << 3)) * 128
                         + (((lane >> 3) & 1) << 4);

    load_stage(0);
    load_stage(1);

    for (int i = 0; i < nIter; i++) {
        CP_WAIT1();
        __syncthreads();

        const uint32_t st  = sbase + (uint32_t)(i % NSTAGE) * STAGEB;
        const uint32_t tAh = st, tAl = st + ATILEB;
        const uint32_t tBh = st + 2 * ATILEB, tBl = tBh + BTILEB;

#pragma unroll
        for (int kc = 0; kc < 4; kc++) {
            const uint32_t kB = (uint32_t)kc * 32;
            uint32_t a[4][4], bh[8][2];
#pragma unroll
            for (int mi = 0; mi < 4; mi++)
                ldm_x4(a[mi], tAh + swz(aRowB + (uint32_t)(mi * 16) * 128 + kB));
#pragma unroll
            for (int np = 0; np < 4; np++) {
                uint32_t r[4];
                ldm_x4(r, tBh + swz(bRowB + (uint32_t)(np * 16) * 128 + kB));
                bh[2 * np][0] = r[0]; bh[2 * np][1] = r[1];
                bh[2 * np + 1][0] = r[2]; bh[2 * np + 1][1] = r[3];
            }
#pragma unroll
            for (int mi = 0; mi < 4; mi++)
#pragma unroll
                for (int ni = 0; ni < 8; ni++)
                    mma16816(acc[mi][ni], a[mi], bh[ni]);          // hi*hi
            {
                uint32_t bl[8][2];
#pragma unroll
                for (int np = 0; np < 4; np++) {
                    uint32_t r[4];
                    ldm_x4(r, tBl + swz(bRowB + (uint32_t)(np * 16) * 128 + kB));
                    bl[2 * np][0] = r[0]; bl[2 * np][1] = r[1];
                    bl[2 * np + 1][0] = r[2]; bl[2 * np + 1][1] = r[3];
                }
#pragma unroll
                for (int mi = 0; mi < 4; mi++)
#pragma unroll
                    for (int ni = 0; ni < 8; ni++)
                        mma16816(acc[mi][ni], a[mi], bl[ni]);      // hi*lo
            }
            if (NPROD == 3) {
#pragma unroll
                for (int mi = 0; mi < 4; mi++)
                    ldm_x4(a[mi], tAl + swz(aRowB + (uint32_t)(mi * 16) * 128 + kB));
#pragma unroll
                for (int mi = 0; mi < 4; mi++)
#pragma unroll
                    for (int ni = 0; ni < 8; ni++)
                        mma16816(acc[mi][ni], a[mi], bh[ni]);      // lo*hi
            }
        }
        __syncthreads();
        if (i + 2 < nIter) load_stage(i + 2);
        else CP_COMMIT();                       // keep wait_group 1 exact
    }

    // ---- epilogue: accum -> smem (fp32, stride 260) -> coalesced global ----
    float* sEpi = (float*)smem;                 // 128 x 260 floats
    __syncthreads();
    {
        const int r0 = warp_m * 64 + (lane >> 2);
        const int c0 = warp_n * 64 + 2 * (lane & 3);
#pragma unroll
        for (int mi = 0; mi < 4; mi++)
#pragma unroll
            for (int ni = 0; ni < 8; ni++) {
                const int rr = r0 + mi * 16;
                const int cc = c0 + ni * 8;
                sEpi[rr * 260 + cc]           = acc[mi][ni][0];
                sEpi[rr * 260 + cc + 1]       = acc[mi][ni][1];
                sEpi[(rr + 8) * 260 + cc]     = acc[mi][ni][2];
                sEpi[(rr + 8) * 260 + cc + 1] = acc[mi][ni][3];
            }
    }
    __syncthreads();

    if (EPI == 2) {
        float* Co = (MODE == 2 && bz == 1) ? CfAlt : Cf;
#pragma unroll
        for (int j = 0; j < 32; j++) {
            const int idx = tid + j * 256;       // 0..8191 float4s
            const int row = idx >> 6, c4 = (idx & 63) << 2;
            float4 v = *reinterpret_cast<const float4*>(&sEpi[row * 260 + c4]);
            v.x *= alpha; v.y *= alpha; v.z *= alpha; v.w *= alpha;
            *reinterpret_cast<float4*>(Co + (size_t)(by * BM + row) * ldc + bx * BN + c4) = v;
        }
    } else {  // EPI == 3: QKV dispatch
        if (wsel < 2) {
            __half* Oh = wsel ? Kh : Qh;
            __half* Ol = wsel ? Kl : Ql;
#pragma unroll
            for (int j = 0; j < 64; j++) {
                const int idx = tid + j * 256;
                const int row = idx >> 7, c2 = (idx & 127) << 1;
                const size_t o = (size_t)(by * BM + row) * SD + bCol0 + c2;
                split_store2(Oh, Ol, o, sEpi[row * 260 + c2], sEpi[row * 260 + c2 + 1]);
            }
        } else {  // V: transposed split store
#pragma unroll
            for (int j = 0; j < 64; j++) {
                const int idx = tid + j * 256;
                const int c = idx >> 6;              // feature in tile, 0..255
                const int r2 = (idx & 63) << 1;      // two consecutive tokens
                const size_t o = (size_t)(bCol0 + c) * SN + by * BM + r2;
                split_store2(Vth, Vtl, o, sEpi[r2 * 260 + c], sEpi[(r2 + 1) * 260 + c]);
            }
        }
    }
}

// ------------------------- split / transpose -------------------------------
__global__ void __launch_bounds__(256)
split_kernel(const float* __restrict__ in, __half* __restrict__ h,
             __half* __restrict__ l, int n)
{
    int i = blockIdx.x * 256 + threadIdx.x;
    if (i < n) {
        float v = in[i];
        __half hh = __float2half(v);
        h[i] = hh;
        l[i] = __float2half(v - __half2float(hh));
    }
}

__global__ void __launch_bounds__(1024)
tsplit_kernel(const float* __restrict__ W, __half* __restrict__ Th,
              __half* __restrict__ Tl)
{
    __shared__ float t[32][33];
    const int bx = blockIdx.x, by = blockIdx.y;
    const int txx = threadIdx.x, tyy = threadIdx.y;
    t[tyy][txx] = W[(size_t)(by * 32 + tyy) * SD + bx * 32 + txx];
    __syncthreads();
    const int o  = bx * 32 + tyy;
    const int i2 = by * 32 + txx;
    const float v = t[txx][tyy];
    __half h = __float2half(v);
    Th[(size_t)o * SD + i2] = h;
    Tl[(size_t)o * SD + i2] = __float2half(v - __half2float(h));
}

// ------------------------- softmax (fp32 -> Ph only) -----------------------
__global__ void __launch_bounds__(256)
softmax_kernel(const float* __restrict__ S, __half* __restrict__ Ph,
               const int* __restrict__ maskedp)
{
    __shared__ float sh[SN];
    __shared__ float red[256];
    const int r = blockIdx.x;
    const int msk = *maskedp;
    const int lim = msk ? (r + 1) : SN;
    const int limw = msk ? ((lim + 127) & ~127) : SN;   // PV never reads past this
    const int tid = threadIdx.x;

    float m = -CUDART_INF_F;
    for (int j = tid; j < lim; j += 256) {
        float v = S[(size_t)r * SN + j];
        sh[j] = v;
        m = fmaxf(m, v);
    }
    red[tid] = m; __syncthreads();
    for (int s = 128; s > 0; s >>= 1) {
        if (tid < s) red[tid] = fmaxf(red[tid], red[tid + s]);
        __syncthreads();
    }
    const float rowmax = red[0]; __syncthreads();

    float sum = 0.0f;
    for (int j = tid; j < lim; j += 256) {
        float e = expf(sh[j] - rowmax);
        sh[j] = e;
        sum += e;
    }
    red[tid] = sum; __syncthreads();
    for (int s = 128; s > 0; s >>= 1) {
        if (tid < s) red[tid] += red[tid + s];
        __syncthreads();
    }
    const float inv = 1.0f / red[0]; __syncthreads();

    for (int j = tid; j < limw; j += 256) {
        float p = (j < lim) ? sh[j] * inv : 0.0f;
        Ph[(size_t)r * SN + j] = __float2half(p);
    }
}

// ------------------------- PV split-K reduce -------------------------------
__global__ void __launch_bounds__(256)
add_kernel(float* __restrict__ out, const float* __restrict__ part)
{
    const size_t i = ((size_t)2048 * SD) + ((size_t)blockIdx.x * 256 + threadIdx.x) * 4;
    float4 a = *reinterpret_cast<const float4*>(out + i);
    float4 b = *reinterpret_cast<const float4*>(part + i);
    a.x += b.x; a.y += b.y; a.z += b.z; a.w += b.w;
    *reinterpret_cast<float4*>(out + i) = a;
}

// ------------------------- host --------------------------------------------
extern "C" void kernel_launch(void* const* d_in, const int* in_sizes, int n_in,
                              void* d_out, int out_size)
{
    (void)in_sizes; (void)n_in; (void)out_size;
    const float* x      = (const float*)d_in[0];
    const float* Wq     = (const float*)d_in[1];
    const float* Wk     = (const float*)d_in[2];
    const float* Wv     = (const float*)d_in[3];
    const int*   masked = (const int*)d_in[4];
    float* out = (float*)d_out;

    float *S, *O2;
    __half *xh, *xl, *Wth, *Wtl, *Qh, *Ql, *Kh, *Kl, *Vth, *Vtl, *Ph;
    cudaGetSymbolAddress((void**)&S,   g_S);
    cudaGetSymbolAddress((void**)&O2,  g_O2);
    cudaGetSymbolAddress((void**)&xh,  g_xh);
    cudaGetSymbolAddress((void**)&xl,  g_xl);
    cudaGetSymbolAddress((void**)&Wth, g_Wth);
    cudaGetSymbolAddress((void**)&Wtl, g_Wtl);
    cudaGetSymbolAddress((void**)&Qh,  g_Qh);
    cudaGetSymbolAddress((void**)&Ql,  g_Ql);
    cudaGetSymbolAddress((void**)&Kh,  g_Kh);
    cudaGetSymbolAddress((void**)&Kl,  g_Kl);
    cudaGetSymbolAddress((void**)&Vth, g_Vth);
    cudaGetSymbolAddress((void**)&Vtl, g_Vtl);
    cudaGetSymbolAddress((void**)&Ph,  g_Ph);

    cudaFuncSetAttribute(mm_kernel<0,3,3>, cudaFuncAttributeMaxDynamicSharedMemorySize, SMEMB);
    cudaFuncSetAttribute(mm_kernel<1,2,3>, cudaFuncAttributeMaxDynamicSharedMemorySize, SMEMB);
    cudaFuncSetAttribute(mm_kernel<2,2,2>, cudaFuncAttributeMaxDynamicSharedMemorySize, SMEMB);

    // launches 1-4
    split_kernel<<<(SN * SD + 255) / 256, 256>>>(x, xh, xl, SN * SD);
    dim3 tg(32, 32), tb(32, 32);
    tsplit_kernel<<<tg, tb>>>(Wq, Wth + 0 * SD * SD, Wtl + 0 * SD * SD);
    tsplit_kernel<<<tg, tb>>>(Wk, Wth + 1 * SD * SD, Wtl + 1 * SD * SD);
    tsplit_kernel<<<tg, tb>>>(Wv, Wth + 2 * SD * SD, Wtl + 2 * SD * SD);

    const float scale = 1.0f / 32.0f;

    // launch 5: fused QKV projections (12 = 3 weights x 4 col tiles)
    dim3 gqkv(12, SN / BM);
    mm_kernel<0,3,3><<<gqkv, 256, SMEMB>>>(xh, xl, SD, Wth, Wtl, SD, SD, 1.0f,
                                           nullptr, nullptr, Qh, Ql, Kh, Kl, Vth, Vtl,
                                           0, masked);
    // launch 6: scores (ncu -s 5 -c 1 captures this one)
    dim3 gs(SN / BN, SN / BM);
    mm_kernel<1,2,3><<<gs, 256, SMEMB>>>(Qh, Ql, SD, Kh, Kl, SD, SD, scale,
                                         S, nullptr, nullptr, nullptr, nullptr, nullptr,
                                         nullptr, nullptr, SN, masked);
    softmax_kernel<<<SN, 256>>>(S, Ph, masked);
    dim3 gv(SD / BN, SN / BM, 2);
    mm_kernel<2,2,2><<<gv, 256, SMEMB>>>(Ph, Ph, SN, Vth, Vtl, SN, SN, 1.0f,
                                         out, O2, nullptr, nullptr, nullptr, nullptr,
                                         nullptr, nullptr, SD, masked);
    add_kernel<<<2048, 256>>>(out, O2);
}